// round 2
// baseline (speedup 1.0000x reference)
#include <cuda_runtime.h>
#include <math.h>

// Problem dims
#define N_  128
#define M_  2048
#define DX_ 64
#define DY_ 8
#define DU_ 256
#define DZ_ 256
#define TM  64   // m-tile per block in main kernel

// ---------------- device scratch (static, no allocations) ----------------
__device__ __align__(16) float g_sp1[DZ_ * DZ_];   // softplus(Wz1)
__device__ __align__(16) float g_gy0[N_ * DY_];
__device__ __align__(16) float g_c0 [N_ * DZ_];
__device__ __align__(16) float g_gz1[N_ * DZ_];
__device__ __align__(16) float g_gy1[N_ * DY_];
__device__ __align__(16) float g_c1 [N_ * DZ_];
__device__ __align__(16) float g_gk2[N_ * DZ_];    // gz2 * softplus(Wz2)
__device__ __align__(16) float g_w2d[N_ * DY_];    // gy2 * Wy2
__device__ __align__(16) float g_c2 [N_];
__device__ __align__(16) float g_slack[N_ * M_];

__device__ __forceinline__ float softplus_f(float x) {
    return fmaxf(x, 0.f) + log1pf(expf(-fabsf(x)));
}

// ---------------- kernel 0: softplus(Wz1) ----------------
__global__ void sp1_kernel(const float* __restrict__ Wz1) {
    int i = blockIdx.x * 256 + threadIdx.x;
    g_sp1[i] = softplus_f(Wz1[i]);
}

// ---------------- kernel 1: per-n setup ----------------
__global__ void setup_kernel(
    const float* __restrict__ X,
    const float* __restrict__ Wt0,  const float* __restrict__ bt0,
    const float* __restrict__ Wt1,  const float* __restrict__ bt1,
    const float* __restrict__ Wyu0, const float* __restrict__ byu0,
    const float* __restrict__ Wu0,  const float* __restrict__ b0,
    const float* __restrict__ Wzu1, const float* __restrict__ bzu1,
    const float* __restrict__ Wyu1, const float* __restrict__ byu1,
    const float* __restrict__ Wu1,  const float* __restrict__ b1,
    const float* __restrict__ Wzu2, const float* __restrict__ bzu2,
    const float* __restrict__ Wz2,
    const float* __restrict__ Wyu2, const float* __restrict__ byu2,
    const float* __restrict__ Wy2,
    const float* __restrict__ Wu2,  const float* __restrict__ b2)
{
    __shared__ float xs[DX_], u1s[DU_], u2s[DU_], red[256];
    const int n = blockIdx.x;
    const int k = threadIdx.x;

    if (k < DX_) xs[k] = X[n * DX_ + k];
    __syncthreads();

    // u1 = relu(X @ Wt0^T + bt0)
    float s = bt0[k];
    #pragma unroll 8
    for (int d = 0; d < DX_; d++) s = fmaf(xs[d], Wt0[k * DX_ + d], s);
    u1s[k] = fmaxf(s, 0.f);
    __syncthreads();

    // u2 = relu(u1 @ Wt1^T + bt1)
    s = bt1[k];
    #pragma unroll 8
    for (int z = 0; z < DU_; z++) s = fmaf(u1s[z], Wt1[k * DU_ + z], s);
    float u2v = fmaxf(s, 0.f);
    u2s[k] = u2v;

    // gy0, gy1 (only 8 threads)
    if (k < DY_) {
        float t = byu0[k];
        #pragma unroll 8
        for (int d = 0; d < DX_; d++) t = fmaf(xs[d], Wyu0[k * DX_ + d], t);
        g_gy0[n * DY_ + k] = t;
        t = byu1[k];
        #pragma unroll 8
        for (int z = 0; z < DU_; z++) t = fmaf(u1s[z], Wyu1[k * DU_ + z], t);
        g_gy1[n * DY_ + k] = t;
    }
    // c0 = X @ Wu0^T + b0
    s = b0[k];
    #pragma unroll 8
    for (int d = 0; d < DX_; d++) s = fmaf(xs[d], Wu0[k * DX_ + d], s);
    g_c0[n * DZ_ + k] = s;
    // gz1 = relu(u1 @ Wzu1^T + bzu1)
    s = bzu1[k];
    #pragma unroll 8
    for (int z = 0; z < DU_; z++) s = fmaf(u1s[z], Wzu1[k * DU_ + z], s);
    g_gz1[n * DZ_ + k] = fmaxf(s, 0.f);
    // c1 = u1 @ Wu1^T + b1
    s = b1[k];
    #pragma unroll 8
    for (int z = 0; z < DU_; z++) s = fmaf(u1s[z], Wu1[k * DU_ + z], s);
    g_c1[n * DZ_ + k] = s;
    __syncthreads();

    // gk2 = relu(u2 @ Wzu2^T + bzu2) * softplus(Wz2)
    s = bzu2[k];
    #pragma unroll 8
    for (int z = 0; z < DU_; z++) s = fmaf(u2s[z], Wzu2[k * DU_ + z], s);
    g_gk2[n * DZ_ + k] = fmaxf(s, 0.f) * softplus_f(Wz2[k]);

    // w2d = (u2 @ Wyu2^T + byu2) * Wy2
    if (k < DY_) {
        float t = byu2[k];
        #pragma unroll 8
        for (int z = 0; z < DU_; z++) t = fmaf(u2s[z], Wyu2[k * DU_ + z], t);
        g_w2d[n * DY_ + k] = t * Wy2[k];
    }

    // c2 = u2 @ Wu2 + b2  (block reduce)
    red[k] = u2v * Wu2[k];
    __syncthreads();
    for (int st = 128; st > 0; st >>= 1) {
        if (k < st) red[k] += red[k + st];
        __syncthreads();
    }
    if (k == 0) g_c2[n] = red[0] + b2[0];
}

// ---------------- kernel 2: main pairwise GEMM + slack ----------------
// grid = (M_/TM, N_), block = 256 threads.
// Thread (mg,km): mg = warp id (8 m-rows), km = lane (8 k-cols) -> 8x8 tile.
__global__ __launch_bounds__(256, 2) void main_kernel(
    const float* __restrict__ U,
    const float* __restrict__ Y,
    const float* __restrict__ Wy0,
    const float* __restrict__ Wy1)
{
    __shared__ __align__(16) float Um[TM * DY_];        // U tile [64][8]
    __shared__ __align__(16) float wy0fs[DZ_ * DY_];    // Wy0[z][d]*gy0[d]
    __shared__ __align__(16) float c0s[DZ_], gz1s[DZ_];
    __shared__ __align__(16) float g1s[DY_], yws[DY_];
    __shared__ __align__(16) float Wcs[8 * DZ_];        // W chunk transposed [j][k]
    __shared__ __align__(16) float a_cs[8 * TM];        // a chunk [j][m]

    const int n   = blockIdx.y;
    const int m0  = blockIdx.x * TM;
    const int tid = threadIdx.x;
    const int mg  = tid >> 5;   // warp id, owns m rows mg*8..mg*8+7
    const int km  = tid & 31;   // lane, owns k cols km*8..km*8+7
    const int mg8 = mg * 8, km8 = km * 8;

    // --- preload per-n data ---
    c0s[tid]  = g_c0 [n * DZ_ + tid];
    gz1s[tid] = g_gz1[n * DZ_ + tid];
    if (tid < DY_) {
        g1s[tid] = g_gy1[n * DY_ + tid];
        yws[tid] = Y[n * DY_ + tid] - g_w2d[n * DY_ + tid];
    }
    Um[tid]       = U[m0 * DY_ + tid];
    Um[tid + 256] = U[m0 * DY_ + tid + 256];
    __syncthreads();

    // wy0fs[z][d] = Wy0[z][d] * gy0[n][d]   (vectorized, conflict-free)
    {
        float g0[DY_];
        #pragma unroll
        for (int d = 0; d < DY_; d++) g0[d] = g_gy0[n * DY_ + d];
        float4 wa = *(const float4*)&Wy0[tid * DY_];
        float4 wb = *(const float4*)&Wy0[tid * DY_ + 4];
        float4 ra = make_float4(wa.x * g0[0], wa.y * g0[1], wa.z * g0[2], wa.w * g0[3]);
        float4 rb = make_float4(wb.x * g0[4], wb.y * g0[5], wb.z * g0[6], wb.w * g0[7]);
        *(float4*)&wy0fs[tid * DY_]     = ra;
        *(float4*)&wy0fs[tid * DY_ + 4] = rb;
    }
    __syncthreads();

    float acc[8][8];
    #pragma unroll
    for (int i = 0; i < 8; i++)
        #pragma unroll
        for (int kk = 0; kk < 8; kk++) acc[i][kk] = 0.f;

    // 32 real z-chunks + 1 pseudo chunk (the rank-8 t1 term)
    for (int zc = 0; zc <= 32; ++zc) {
        if (zc < 32) {
            // stage W chunk: Wcs[j][k] = sp1[k][zc*8+j]
            const float4 w0 = *(const float4*)&g_sp1[tid * DZ_ + zc * 8];
            const float4 w1 = *(const float4*)&g_sp1[tid * DZ_ + zc * 8 + 4];
            Wcs[0 * DZ_ + tid] = w0.x; Wcs[1 * DZ_ + tid] = w0.y;
            Wcs[2 * DZ_ + tid] = w0.z; Wcs[3 * DZ_ + tid] = w0.w;
            Wcs[4 * DZ_ + tid] = w1.x; Wcs[5 * DZ_ + tid] = w1.y;
            Wcs[6 * DZ_ + tid] = w1.z; Wcs[7 * DZ_ + tid] = w1.w;
            // produce a chunk: a[m][z] = relu(sum_d U[m,d]*wy0f[z,d] + c0[z]) * gz1[z]
            #pragma unroll
            for (int e = 0; e < 2; e++) {
                int id = tid + e * 256;
                int j = id >> 6, m = id & 63;
                int z = zc * 8 + j;
                const float4 uu0 = *(const float4*)&Um[m * 8];
                const float4 uu1 = *(const float4*)&Um[m * 8 + 4];
                const float4 f0  = *(const float4*)&wy0fs[z * 8];
                const float4 f1  = *(const float4*)&wy0fs[z * 8 + 4];
                float v = c0s[z];
                v = fmaf(uu0.x, f0.x, v); v = fmaf(uu0.y, f0.y, v);
                v = fmaf(uu0.z, f0.z, v); v = fmaf(uu0.w, f0.w, v);
                v = fmaf(uu1.x, f1.x, v); v = fmaf(uu1.y, f1.y, v);
                v = fmaf(uu1.z, f1.z, v); v = fmaf(uu1.w, f1.w, v);
                a_cs[j * 64 + m] = fmaxf(v, 0.f) * gz1s[z];
            }
        } else {
            // pseudo chunk: Wc[j][k] = Wy1[k][j]*gy1[j], a[j][m] = U[m][j]
            const float4 wr0 = *(const float4*)&Wy1[tid * 8];
            const float4 wr1 = *(const float4*)&Wy1[tid * 8 + 4];
            Wcs[0 * DZ_ + tid] = wr0.x * g1s[0]; Wcs[1 * DZ_ + tid] = wr0.y * g1s[1];
            Wcs[2 * DZ_ + tid] = wr0.z * g1s[2]; Wcs[3 * DZ_ + tid] = wr0.w * g1s[3];
            Wcs[4 * DZ_ + tid] = wr1.x * g1s[4]; Wcs[5 * DZ_ + tid] = wr1.y * g1s[5];
            Wcs[6 * DZ_ + tid] = wr1.z * g1s[6]; Wcs[7 * DZ_ + tid] = wr1.w * g1s[7];
            #pragma unroll
            for (int e = 0; e < 2; e++) {
                int id = tid + e * 256;
                int j = id >> 6, m = id & 63;
                a_cs[j * 64 + m] = Um[m * 8 + j];
            }
        }
        __syncthreads();

        #pragma unroll
        for (int j = 0; j < 8; j++) {
            const float4 a0 = *(const float4*)&a_cs[j * 64 + mg8];
            const float4 a1 = *(const float4*)&a_cs[j * 64 + mg8 + 4];
            const float4 w0 = *(const float4*)&Wcs[j * DZ_ + km8];
            const float4 w1 = *(const float4*)&Wcs[j * DZ_ + km8 + 4];
            float av[8] = {a0.x, a0.y, a0.z, a0.w, a1.x, a1.y, a1.z, a1.w};
            float wv[8] = {w0.x, w0.y, w0.z, w0.w, w1.x, w1.y, w1.z, w1.w};
            #pragma unroll
            for (int i = 0; i < 8; i++)
                #pragma unroll
                for (int kk = 0; kk < 8; kk++)
                    acc[i][kk] = fmaf(av[i], wv[kk], acc[i][kk]);
        }
        __syncthreads();
    }

    // --- epilogue: z2 = relu(acc + c1), phi = sum_k z2*gk2, slack ---
    const float4 c1a = *(const float4*)&g_c1 [n * DZ_ + km8];
    const float4 c1b = *(const float4*)&g_c1 [n * DZ_ + km8 + 4];
    const float4 gka = *(const float4*)&g_gk2[n * DZ_ + km8];
    const float4 gkb = *(const float4*)&g_gk2[n * DZ_ + km8 + 4];
    const float c1r[8] = {c1a.x, c1a.y, c1a.z, c1a.w, c1b.x, c1b.y, c1b.z, c1b.w};
    const float gkr[8] = {gka.x, gka.y, gka.z, gka.w, gkb.x, gkb.y, gkb.z, gkb.w};
    const float c2n = g_c2[n];

    #pragma unroll
    for (int i = 0; i < 8; i++) {
        float phi = 0.f;
        #pragma unroll
        for (int kk = 0; kk < 8; kk++) {
            float z2 = fmaxf(acc[i][kk] + c1r[kk], 0.f);
            phi = fmaf(z2, gkr[kk], phi);
        }
        #pragma unroll
        for (int off = 16; off; off >>= 1)
            phi += __shfl_xor_sync(0xffffffffu, phi, off);
        if (km == 0) {
            int m = mg8 + i;
            float sl = -c2n - phi;
            #pragma unroll
            for (int d = 0; d < DY_; d++)
                sl = fmaf(Um[m * 8 + d], yws[d], sl);
            g_slack[n * M_ + m0 + m] = sl;
        }
    }
}

// ---------------- kernel 3: row-wise stable logsumexp ----------------
__global__ void lse_kernel(float* __restrict__ out) {
    __shared__ float wred[8];
    __shared__ float bmax_s;
    const int n = blockIdx.x, tid = threadIdx.x;
    const int lane = tid & 31, warp = tid >> 5;

    float s[8];
    #pragma unroll
    for (int i = 0; i < 8; i++) s[i] = g_slack[n * M_ + tid + i * 256];

    float mx = s[0];
    #pragma unroll
    for (int i = 1; i < 8; i++) mx = fmaxf(mx, s[i]);
    #pragma unroll
    for (int off = 16; off; off >>= 1)
        mx = fmaxf(mx, __shfl_xor_sync(0xffffffffu, mx, off));
    if (lane == 0) wred[warp] = mx;
    __syncthreads();
    if (tid == 0) {
        float m2 = wred[0];
        #pragma unroll
        for (int w = 1; w < 8; w++) m2 = fmaxf(m2, wred[w]);
        bmax_s = m2;
    }
    __syncthreads();
    const float bmax = bmax_s;

    float sum = 0.f;
    #pragma unroll
    for (int i = 0; i < 8; i++) sum += expf((s[i] - bmax) * 100.f);
    #pragma unroll
    for (int off = 16; off; off >>= 1)
        sum += __shfl_xor_sync(0xffffffffu, sum, off);
    __syncthreads();          // wred reuse
    if (lane == 0) wred[warp] = sum;
    __syncthreads();
    if (tid == 0) {
        float tot = 0.f;
        #pragma unroll
        for (int w = 0; w < 8; w++) tot += wred[w];
        out[n] = 0.01f * (logf(tot) - logf(2048.0f)) + bmax;
    }
}

// ---------------- launch ----------------
extern "C" void kernel_launch(void* const* d_in, const int* in_sizes, int n_in,
                              void* d_out, int out_size) {
    const float* X    = (const float*)d_in[0];
    const float* U    = (const float*)d_in[1];
    const float* Y    = (const float*)d_in[2];
    const float* Wt0  = (const float*)d_in[3];
    const float* bt0  = (const float*)d_in[4];
    const float* Wt1  = (const float*)d_in[5];
    const float* bt1  = (const float*)d_in[6];
    const float* Wyu0 = (const float*)d_in[7];
    const float* byu0 = (const float*)d_in[8];
    const float* Wy0  = (const float*)d_in[9];
    const float* Wu0  = (const float*)d_in[10];
    const float* b0   = (const float*)d_in[11];
    const float* Wzu1 = (const float*)d_in[12];
    const float* bzu1 = (const float*)d_in[13];
    const float* Wz1  = (const float*)d_in[14];
    const float* Wyu1 = (const float*)d_in[15];
    const float* byu1 = (const float*)d_in[16];
    const float* Wy1  = (const float*)d_in[17];
    const float* Wu1  = (const float*)d_in[18];
    const float* b1   = (const float*)d_in[19];
    const float* Wzu2 = (const float*)d_in[20];
    const float* bzu2 = (const float*)d_in[21];
    const float* Wz2  = (const float*)d_in[22];
    const float* Wyu2 = (const float*)d_in[23];
    const float* byu2 = (const float*)d_in[24];
    const float* Wy2  = (const float*)d_in[25];
    const float* Wu2  = (const float*)d_in[26];
    const float* b2   = (const float*)d_in[27];

    sp1_kernel<<<256, 256>>>(Wz1);
    setup_kernel<<<128, 256>>>(X, Wt0, bt0, Wt1, bt1, Wyu0, byu0, Wu0, b0,
                               Wzu1, bzu1, Wyu1, byu1, Wu1, b1,
                               Wzu2, bzu2, Wz2, Wyu2, byu2, Wy2, Wu2, b2);
    dim3 grid(M_ / TM, N_);
    main_kernel<<<grid, 256>>>(U, Y, Wy0, Wy1);
    lse_kernel<<<128, 256>>>((float*)d_out);
}

// round 6
// speedup vs baseline: 2.5483x; 2.5483x over previous
#include <cuda_runtime.h>
#include <math.h>
#include <stdint.h>

// Problem dims
#define N_  128
#define M_  2048
#define DX_ 64
#define DY_ 8
#define DU_ 256
#define DZ_ 256

// ---------------- device scratch (static, no allocations) ----------------
__device__ __align__(16) float g_sp1[DZ_ * DZ_];   // tf32(softplus(Wz1))  [k][z]
__device__ __align__(16) float g_gy0[N_ * DY_];
__device__ __align__(16) float g_c0 [N_ * DZ_];
__device__ __align__(16) float g_gz1[N_ * DZ_];
__device__ __align__(16) float g_gy1[N_ * DY_];
__device__ __align__(16) float g_c1 [N_ * DZ_];
__device__ __align__(16) float g_gk2[N_ * DZ_];    // gz2 * softplus(Wz2)
__device__ __align__(16) float g_w2d[N_ * DY_];    // gy2 * Wy2
__device__ __align__(16) float g_c2 [N_];
__device__ __align__(16) float g_phiA[N_ * M_];    // partial phi, k 0..127
__device__ __align__(16) float g_phiB[N_ * M_];    // partial phi, k 128..255

__device__ __forceinline__ float softplus_f(float x) {
    return fmaxf(x, 0.f) + log1pf(expf(-fabsf(x)));
}
__device__ __forceinline__ float tf32r(float x) {   // round-to-nearest tf32
    uint32_t u;
    asm("cvt.rna.tf32.f32 %0, %1;" : "=r"(u) : "f"(x));
    return __uint_as_float(u);
}

#define CP_ASYNC16(dst, src) \
    asm volatile("cp.async.cg.shared.global [%0], [%1], 16;" \
        :: "r"((uint32_t)(dst)), "l"(src) : "memory")
#define CP_COMMIT() asm volatile("cp.async.commit_group;" ::: "memory")
#define CP_WAIT0()  asm volatile("cp.async.wait_group 0;" ::: "memory")

__device__ __forceinline__ uint32_t smem_u32(const void* p) {
    uint32_t a;
    asm("{ .reg .u64 t; cvta.to.shared.u64 t, %1; cvt.u32.u64 %0, t; }"
        : "=r"(a) : "l"(p));
    return a;
}

// m16n8k8 tf32 MMA: D[16,8] += A[16,8] * B[8,8]
__device__ __forceinline__ void mma_tf32(float* c, const uint32_t* a,
                                         uint32_t b0, uint32_t b1) {
    asm volatile(
        "mma.sync.aligned.m16n8k8.row.col.f32.tf32.tf32.f32 "
        "{%0,%1,%2,%3}, {%4,%5,%6,%7}, {%8,%9}, {%0,%1,%2,%3};"
        : "+f"(c[0]), "+f"(c[1]), "+f"(c[2]), "+f"(c[3])
        : "r"(a[0]), "r"(a[1]), "r"(a[2]), "r"(a[3]), "r"(b0), "r"(b1));
}

// ---------------- kernel 0: tf32(softplus(Wz1)) ----------------
__global__ void sp1_kernel(const float* __restrict__ Wz1) {
    int i = blockIdx.x * 256 + threadIdx.x;
    g_sp1[i] = tf32r(softplus_f(Wz1[i]));
}

// ---------------- kernel 1: per-n setup ----------------
__global__ void setup_kernel(
    const float* __restrict__ X,
    const float* __restrict__ Wt0,  const float* __restrict__ bt0,
    const float* __restrict__ Wt1,  const float* __restrict__ bt1,
    const float* __restrict__ Wyu0, const float* __restrict__ byu0,
    const float* __restrict__ Wu0,  const float* __restrict__ b0,
    const float* __restrict__ Wzu1, const float* __restrict__ bzu1,
    const float* __restrict__ Wyu1, const float* __restrict__ byu1,
    const float* __restrict__ Wu1,  const float* __restrict__ b1,
    const float* __restrict__ Wzu2, const float* __restrict__ bzu2,
    const float* __restrict__ Wz2,
    const float* __restrict__ Wyu2, const float* __restrict__ byu2,
    const float* __restrict__ Wy2,
    const float* __restrict__ Wu2,  const float* __restrict__ b2)
{
    __shared__ float xs[DX_], u1s[DU_], u2s[DU_], red[256];
    const int n = blockIdx.x;
    const int k = threadIdx.x;

    if (k < DX_) xs[k] = X[n * DX_ + k];
    __syncthreads();

    float s = bt0[k];
    #pragma unroll 8
    for (int d = 0; d < DX_; d++) s = fmaf(xs[d], Wt0[k * DX_ + d], s);
    u1s[k] = fmaxf(s, 0.f);
    __syncthreads();

    s = bt1[k];
    #pragma unroll 8
    for (int z = 0; z < DU_; z++) s = fmaf(u1s[z], Wt1[k * DU_ + z], s);
    float u2v = fmaxf(s, 0.f);
    u2s[k] = u2v;

    if (k < DY_) {
        float t = byu0[k];
        #pragma unroll 8
        for (int d = 0; d < DX_; d++) t = fmaf(xs[d], Wyu0[k * DX_ + d], t);
        g_gy0[n * DY_ + k] = t;
        t = byu1[k];
        #pragma unroll 8
        for (int z = 0; z < DU_; z++) t = fmaf(u1s[z], Wyu1[k * DU_ + z], t);
        g_gy1[n * DY_ + k] = t;
    }
    s = b0[k];
    #pragma unroll 8
    for (int d = 0; d < DX_; d++) s = fmaf(xs[d], Wu0[k * DX_ + d], s);
    g_c0[n * DZ_ + k] = s;
    s = bzu1[k];
    #pragma unroll 8
    for (int z = 0; z < DU_; z++) s = fmaf(u1s[z], Wzu1[k * DU_ + z], s);
    g_gz1[n * DZ_ + k] = fmaxf(s, 0.f);
    s = b1[k];
    #pragma unroll 8
    for (int z = 0; z < DU_; z++) s = fmaf(u1s[z], Wu1[k * DU_ + z], s);
    g_c1[n * DZ_ + k] = s;
    __syncthreads();

    s = bzu2[k];
    #pragma unroll 8
    for (int z = 0; z < DU_; z++) s = fmaf(u2s[z], Wzu2[k * DU_ + z], s);
    g_gk2[n * DZ_ + k] = fmaxf(s, 0.f) * softplus_f(Wz2[k]);

    if (k < DY_) {
        float t = byu2[k];
        #pragma unroll 8
        for (int z = 0; z < DU_; z++) t = fmaf(u2s[z], Wyu2[k * DU_ + z], t);
        g_w2d[n * DY_ + k] = t * Wy2[k];
    }

    red[k] = u2v * Wu2[k];
    __syncthreads();
    for (int st = 128; st > 0; st >>= 1) {
        if (k < st) red[k] += red[k + st];
        __syncthreads();
    }
    if (k == 0) g_c2[n] = red[0] + b2[0];
}

// ---------------- kernel 2: HMMA tf32 GEMM + partial phi ----------------
// grid = (16, 2, 128): x -> 128-row m-tile, y -> k-half (128 cols), z -> n.
// CTA: 128m x 128k; 8 warps, each 32m x 64k (2x4 m16n8k8 tiles, 4 z-subs).
// K loop: 8 chunks of 32 z + 1 pseudo chunk (rank-8 t1 term), double buffered.

// smem float offsets
#define F_WC    0        // 2 x (128 rows x 36)   W chunk  [ko][z] stride 36
#define F_A     9216     // 2 x (128 rows x 36)   A chunk  [m][z]  stride 36
#define F_WY0F  18432    // 256 x 12
#define F_C0    21504    // 256
#define F_GZ1   21760    // 256
#define F_C1    22016    // 128
#define F_GK2   22144    // 128
#define F_GY1   22272    // 16
#define F_PHI   22288    // 256
#define SMEM_FLOATS 22544
#define SMEM_BYTES  (SMEM_FLOATS * 4)

extern __shared__ __align__(16) float sm[];

__global__ __launch_bounds__(256, 2) void main_mma_kernel(
    const float* __restrict__ U,
    const float* __restrict__ Wy0,
    const float* __restrict__ Wy1)
{
    const int tid  = threadIdx.x;
    const int lane = tid & 31;
    const int wid  = tid >> 5;
    const int g    = lane >> 2;      // groupID (0..7)
    const int t4   = lane & 3;       // threadID_in_group
    const int wm   = wid & 3;        // warp m-group (32 rows each)
    const int wn   = wid >> 2;       // warp n-group (64 cols each)
    const int n    = blockIdx.z;
    const int nh   = blockIdx.y;
    const int m0   = blockIdx.x * 128;
    const int k0   = nh * 128;

    float* Wc   = sm + F_WC;
    float* Asm  = sm + F_A;
    float* wy0f = sm + F_WY0F;
    float* c0s  = sm + F_C0;
    float* gz1s = sm + F_GZ1;
    float* c1s  = sm + F_C1;
    float* gk2s = sm + F_GK2;
    float* gy1s = sm + F_GY1;
    float* phiB = sm + F_PHI;
    const uint32_t sbWc = smem_u32(Wc);

    // ---- prologue ----
    c0s[tid]  = g_c0 [n * DZ_ + tid];
    gz1s[tid] = g_gz1[n * DZ_ + tid];
    if (tid < 128) {
        c1s[tid]  = g_c1 [n * DZ_ + k0 + tid];
        gk2s[tid] = g_gk2[n * DZ_ + k0 + tid];
    }
    if (tid < DY_) gy1s[tid] = g_gy1[n * DY_ + tid];
    {   // wy0f[z][d] = Wy0[z][d] * gy0[n][d], stride 12
        const int z = tid;
        float4 wa = *(const float4*)&Wy0[z * 8];
        float4 wb = *(const float4*)&Wy0[z * 8 + 4];
        float4 ga = *(const float4*)&g_gy0[n * DY_];
        float4 gb = *(const float4*)&g_gy0[n * DY_ + 4];
        *(float4*)&wy0f[z * 12]     = make_float4(wa.x*ga.x, wa.y*ga.y, wa.z*ga.z, wa.w*ga.w);
        *(float4*)&wy0f[z * 12 + 4] = make_float4(wb.x*gb.x, wb.y*gb.y, wb.z*gb.z, wb.w*gb.w);
    }
    // this thread's A-fill assignment: one m row, 16 z slots (parity-interleaved)
    const int am = tid >> 1;         // local m row (0..127)
    const int ab = tid & 1;          // z parity
    float ur[8];
    {
        float4 u0 = *(const float4*)&U[(m0 + am) * 8];
        float4 u1 = *(const float4*)&U[(m0 + am) * 8 + 4];
        ur[0]=u0.x; ur[1]=u0.y; ur[2]=u0.z; ur[3]=u0.w;
        ur[4]=u1.x; ur[5]=u1.y; ur[6]=u1.z; ur[7]=u1.w;
    }

    // fragment smem offsets (floats, within a buffer)
    int aoff[2], boff[8];
    #pragma unroll
    for (int i = 0; i < 2; ++i) aoff[i] = (wm * 32 + i * 16 + g) * 36 + t4;
    #pragma unroll
    for (int j = 0; j < 8; ++j) boff[j] = (wn * 64 + j * 8 + g) * 36 + t4;

    // kick off W chunk 0 cp.async
    {
        #pragma unroll
        for (int it = 0; it < 4; ++it) {
            int idx = it * 256 + tid;
            int ko = idx >> 3, q = idx & 7;
            CP_ASYNC16(sbWc + (uint32_t)(ko * 144 + q * 16),
                       &g_sp1[(k0 + ko) * DZ_ + q * 4]);
        }
        CP_COMMIT();
    }
    __syncthreads();   // wy0f/c0s/gz1s visible

    // fill A chunk 0
    {
        float* Ab = Asm;  // buf 0
        #pragma unroll
        for (int j = 0; j < 16; ++j) {
            int zl = ab + 2 * j;
            int zg = zl;                    // chunk 0
            float4 w0 = *(const float4*)&wy0f[zg * 12];
            float4 w1 = *(const float4*)&wy0f[zg * 12 + 4];
            float v = c0s[zg];
            v = fmaf(ur[0], w0.x, v); v = fmaf(ur[1], w0.y, v);
            v = fmaf(ur[2], w0.z, v); v = fmaf(ur[3], w0.w, v);
            v = fmaf(ur[4], w1.x, v); v = fmaf(ur[5], w1.y, v);
            v = fmaf(ur[6], w1.z, v); v = fmaf(ur[7], w1.w, v);
            Ab[am * 36 + zl] = tf32r(fmaxf(v, 0.f) * gz1s[zg]);
        }
    }
    CP_WAIT0();
    __syncthreads();

    float acc[2][8][4];
    #pragma unroll
    for (int i = 0; i < 2; ++i)
        #pragma unroll
        for (int j = 0; j < 8; ++j)
            #pragma unroll
            for (int q = 0; q < 4; ++q) acc[i][j][q] = 0.f;

    // ---- main loop: 9 chunks ----
    for (int c = 0; c < 9; ++c) {
        const int buf = c & 1, nb = buf ^ 1;

        // stage next chunk into nb
        if (c < 8) {
            if (c + 1 < 8) {
                const int z0n = (c + 1) * 32;
                #pragma unroll
                for (int it = 0; it < 4; ++it) {
                    int idx = it * 256 + tid;
                    int ko = idx >> 3, q = idx & 7;
                    CP_ASYNC16(sbWc + (uint32_t)(nb * 18432 + ko * 144 + q * 16),
                               &g_sp1[(k0 + ko) * DZ_ + z0n + q * 4]);
                }
                CP_COMMIT();
                // A chunk c+1
                float* Ab = Asm + nb * 4608;
                #pragma unroll
                for (int j = 0; j < 16; ++j) {
                    int zl = ab + 2 * j;
                    int zg = z0n + zl;
                    float4 w0 = *(const float4*)&wy0f[zg * 12];
                    float4 w1 = *(const float4*)&wy0f[zg * 12 + 4];
                    float v = c0s[zg];
                    v = fmaf(ur[0], w0.x, v); v = fmaf(ur[1], w0.y, v);
                    v = fmaf(ur[2], w0.z, v); v = fmaf(ur[3], w0.w, v);
                    v = fmaf(ur[4], w1.x, v); v = fmaf(ur[5], w1.y, v);
                    v = fmaf(ur[6], w1.z, v); v = fmaf(ur[7], w1.w, v);
                    Ab[am * 36 + zl] = tf32r(fmaxf(v, 0.f) * gz1s[zg]);
                }
            } else {
                // pseudo chunk: A[m][d<8]=tf32(U[m,d]); W[ko][d<8]=tf32(Wy1*gy1)
                float* Ab = Asm + nb * 4608;
                #pragma unroll
                for (int j = 0; j < 16; ++j) {
                    int zl = ab + 2 * j;
                    Ab[am * 36 + zl] = (zl < 8) ? tf32r(ur[zl]) : 0.f;
                }
                float* Wb = Wc + nb * 4608;
                const int ko = tid >> 1;
                #pragma unroll
                for (int j = 0; j < 16; ++j) {
                    int zl = ab + 2 * j;
                    float v = 0.f;
                    if (zl < 8) v = tf32r(Wy1[(k0 + ko) * 8 + zl] * gy1s[zl]);
                    Wb[ko * 36 + zl] = v;
                }
            }
        }

        // MMA on current buffer
        {
            const uint32_t* Au = (const uint32_t*)(Asm + buf * 4608);
            const uint32_t* Wu = (const uint32_t*)(Wc  + buf * 4608);
            #pragma unroll
            for (int zs = 0; zs < 4; ++zs) {
                const int zb = zs * 8;
                uint32_t afr[2][4];
                #pragma unroll
                for (int i = 0; i < 2; ++i) {
                    afr[i][0] = Au[aoff[i] + zb];
                    afr[i][1] = Au[aoff[i] + zb + 288];
                    afr[i][2] = Au[aoff[i] + zb + 4];
                    afr[i][3] = Au[aoff[i] + zb + 292];
                }
                #pragma unroll
                for (int j = 0; j < 8; ++j) {
                    uint32_t b0 = Wu[boff[j] + zb];
                    uint32_t b1 = Wu[boff[j] + zb + 4];
                    mma_tf32(acc[0][j], afr[0], b0, b1);
                    mma_tf32(acc[1][j], afr[1], b0, b1);
                }
            }
        }
        if (c < 7) CP_WAIT0();
        __syncthreads();
    }

    // ---- epilogue: partial phi over this CTA's 128 k ----
    float p[4] = {0.f, 0.f, 0.f, 0.f};
    #pragma unroll
    for (int i = 0; i < 2; ++i) {
        #pragma unroll
        for (int j = 0; j < 8; ++j) {
            const int kc = wn * 64 + j * 8 + 2 * t4;
            float ca = c1s[kc],  cb = c1s[kc + 1];
            float ga = gk2s[kc], gb = gk2s[kc + 1];
            p[i*2+0] = fmaf(fmaxf(acc[i][j][0] + ca, 0.f), ga, p[i*2+0]);
            p[i*2+0] = fmaf(fmaxf(acc[i][j][1] + cb, 0.f), gb, p[i*2+0]);
            p[i*2+1] = fmaf(fmaxf(acc[i][j][2] + ca, 0.f), ga, p[i*2+1]);
            p[i*2+1] = fmaf(fmaxf(acc[i][j][3] + cb, 0.f), gb, p[i*2+1]);
        }
    }
    #pragma unroll
    for (int idx = 0; idx < 4; ++idx) {
        float v = p[idx];
        v += __shfl_xor_sync(0xffffffffu, v, 1);
        v += __shfl_xor_sync(0xffffffffu, v, 2);
        if (t4 == 0) {
            const int i = idx >> 1, s = idx & 1;
            phiB[wn * 128 + wm * 32 + i * 16 + s * 8 + g] = v;
        }
    }
    __syncthreads();
    if (tid < 128) {
        float phi = phiB[tid] + phiB[128 + tid];
        float* dst = nh ? g_phiB : g_phiA;
        dst[n * M_ + m0 + tid] = phi;
    }
}

// ---------------- kernel 3: slack + row-wise stable logsumexp ----------------
__global__ void lse_kernel(const float* __restrict__ U,
                           const float* __restrict__ Y,
                           float* __restrict__ out) {
    __shared__ float yw[8];
    __shared__ float wred[8];
    __shared__ float bmax_s;
    const int n = blockIdx.x, tid = threadIdx.x;
    const int lane = tid & 31, warp = tid >> 5;

    if (tid < 8) yw[tid] = Y[n * DY_ + tid] - g_w2d[n * DY_ + tid];
    __syncthreads();
    const float c2 = g_c2[n];

    float s[8];
    #pragma unroll
    for (int i = 0; i < 8; i++) {
        const int m = i * 256 + tid;
        float4 u0 = *(const float4*)&U[m * 8];
        float4 u1 = *(const float4*)&U[m * 8 + 4];
        float v = -c2 - g_phiA[n * M_ + m] - g_phiB[n * M_ + m];
        v = fmaf(u0.x, yw[0], v); v = fmaf(u0.y, yw[1], v);
        v = fmaf(u0.z, yw[2], v); v = fmaf(u0.w, yw[3], v);
        v = fmaf(u1.x, yw[4], v); v = fmaf(u1.y, yw[5], v);
        v = fmaf(u1.z, yw[6], v); v = fmaf(u1.w, yw[7], v);
        s[i] = v;
    }

    float mx = s[0];
    #pragma unroll
    for (int i = 1; i < 8; i++) mx = fmaxf(mx, s[i]);
    #pragma unroll
    for (int off = 16; off; off >>= 1)
        mx = fmaxf(mx, __shfl_xor_sync(0xffffffffu, mx, off));
    if (lane == 0) wred[warp] = mx;
    __syncthreads();
    if (tid == 0) {
        float m2 = wred[0];
        #pragma unroll
        for (int w = 1; w < 8; w++) m2 = fmaxf(m2, wred[w]);
        bmax_s = m2;
    }
    __syncthreads();
    const float bmax = bmax_s;

    float sum = 0.f;
    #pragma unroll
    for (int i = 0; i < 8; i++) sum += expf((s[i] - bmax) * 100.f);
    #pragma unroll
    for (int off = 16; off; off >>= 1)
        sum += __shfl_xor_sync(0xffffffffu, sum, off);
    __syncthreads();
    if (lane == 0) wred[warp] = sum;
    __syncthreads();
    if (tid == 0) {
        float tot = 0.f;
        #pragma unroll
        for (int w = 0; w < 8; w++) tot += wred[w];
        out[n] = 0.01f * (logf(tot) - logf(2048.0f)) + bmax;
    }
}

// ---------------- launch ----------------
extern "C" void kernel_launch(void* const* d_in, const int* in_sizes, int n_in,
                              void* d_out, int out_size) {
    const float* X    = (const float*)d_in[0];
    const float* U    = (const float*)d_in[1];
    const float* Y    = (const float*)d_in[2];
    const float* Wt0  = (const float*)d_in[3];
    const float* bt0  = (const float*)d_in[4];
    const float* Wt1  = (const float*)d_in[5];
    const float* bt1  = (const float*)d_in[6];
    const float* Wyu0 = (const float*)d_in[7];
    const float* byu0 = (const float*)d_in[8];
    const float* Wy0  = (const float*)d_in[9];
    const float* Wu0  = (const float*)d_in[10];
    const float* b0   = (const float*)d_in[11];
    const float* Wzu1 = (const float*)d_in[12];
    const float* bzu1 = (const float*)d_in[13];
    const float* Wz1  = (const float*)d_in[14];
    const float* Wyu1 = (const float*)d_in[15];
    const float* byu1 = (const float*)d_in[16];
    const float* Wy1  = (const float*)d_in[17];
    const float* Wu1  = (const float*)d_in[18];
    const float* b1   = (const float*)d_in[19];
    const float* Wzu2 = (const float*)d_in[20];
    const float* bzu2 = (const float*)d_in[21];
    const float* Wz2  = (const float*)d_in[22];
    const float* Wyu2 = (const float*)d_in[23];
    const float* byu2 = (const float*)d_in[24];
    const float* Wy2  = (const float*)d_in[25];
    const float* Wu2  = (const float*)d_in[26];
    const float* b2   = (const float*)d_in[27];

    cudaFuncSetAttribute(main_mma_kernel,
                         cudaFuncAttributeMaxDynamicSharedMemorySize, SMEM_BYTES);

    sp1_kernel<<<256, 256>>>(Wz1);
    setup_kernel<<<128, 256>>>(X, Wt0, bt0, Wt1, bt1, Wyu0, byu0, Wu0, b0,
                               Wzu1, bzu1, Wyu1, byu1, Wu1, b1,
                               Wzu2, bzu2, Wz2, Wyu2, byu2, Wy2, Wu2, b2);
    dim3 grid(16, 2, 128);
    main_mma_kernel<<<grid, 256, SMEM_BYTES>>>(U, Wy0, Wy1);
    lse_kernel<<<128, 256>>>(U, Y, (float*)d_out);
}

// round 7
// speedup vs baseline: 2.8641x; 1.1239x over previous
#include <cuda_runtime.h>
#include <cuda_fp16.h>
#include <math.h>
#include <stdint.h>

// Problem dims
#define N_  128
#define M_  2048
#define DX_ 64
#define DY_ 8
#define DU_ 256
#define DZ_ 256

// ---------------- device scratch (static, no allocations) ----------------
__device__ __align__(16) __half g_sp1h[DZ_ * DZ_];  // fp16(softplus(Wz1)) [k][z]
__device__ __align__(16) float g_gy0[N_ * DY_];
__device__ __align__(16) float g_c0 [N_ * DZ_];
__device__ __align__(16) float g_gz1[N_ * DZ_];
__device__ __align__(16) float g_gy1[N_ * DY_];
__device__ __align__(16) float g_c1 [N_ * DZ_];
__device__ __align__(16) float g_gk2[N_ * DZ_];     // gz2 * softplus(Wz2)
__device__ __align__(16) float g_w2d[N_ * DY_];     // gy2 * Wy2
__device__ __align__(16) float g_c2 [N_];
__device__ __align__(16) float g_slack[N_ * M_];

__device__ __forceinline__ float softplus_f(float x) {
    return fmaxf(x, 0.f) + log1pf(expf(-fabsf(x)));
}

#define CP_ASYNC16(dst, src) \
    asm volatile("cp.async.cg.shared.global [%0], [%1], 16;" \
        :: "r"((uint32_t)(dst)), "l"(src) : "memory")
#define CP_COMMIT() asm volatile("cp.async.commit_group;" ::: "memory")
#define CP_WAIT0()  asm volatile("cp.async.wait_group 0;" ::: "memory")

__device__ __forceinline__ uint32_t smem_u32(const void* p) {
    uint32_t a;
    asm("{ .reg .u64 t; cvta.to.shared.u64 t, %1; cvt.u32.u64 %0, t; }"
        : "=r"(a) : "l"(p));
    return a;
}

// m16n8k16 fp16 MMA, fp32 accumulate
__device__ __forceinline__ void mma_f16(float* c, const uint32_t* a,
                                        uint32_t b0, uint32_t b1) {
    asm volatile(
        "mma.sync.aligned.m16n8k16.row.col.f32.f16.f16.f32 "
        "{%0,%1,%2,%3}, {%4,%5,%6,%7}, {%8,%9}, {%0,%1,%2,%3};"
        : "+f"(c[0]), "+f"(c[1]), "+f"(c[2]), "+f"(c[3])
        : "r"(a[0]), "r"(a[1]), "r"(a[2]), "r"(a[3]), "r"(b0), "r"(b1));
}

__device__ __forceinline__ uint32_t pack_h2(float lo, float hi) {
    __half2 h = __floats2half2_rn(lo, hi);
    return *(uint32_t*)&h;
}

// ---------------- kernel 0: fp16(softplus(Wz1)) ----------------
__global__ void sp1_kernel(const float* __restrict__ Wz1) {
    int i = blockIdx.x * 256 + threadIdx.x;
    g_sp1h[i] = __float2half_rn(softplus_f(Wz1[i]));
}

// ---------------- kernel 1: per-n setup (unchanged) ----------------
__global__ void setup_kernel(
    const float* __restrict__ X,
    const float* __restrict__ Wt0,  const float* __restrict__ bt0,
    const float* __restrict__ Wt1,  const float* __restrict__ bt1,
    const float* __restrict__ Wyu0, const float* __restrict__ byu0,
    const float* __restrict__ Wu0,  const float* __restrict__ b0,
    const float* __restrict__ Wzu1, const float* __restrict__ bzu1,
    const float* __restrict__ Wyu1, const float* __restrict__ byu1,
    const float* __restrict__ Wu1,  const float* __restrict__ b1,
    const float* __restrict__ Wzu2, const float* __restrict__ bzu2,
    const float* __restrict__ Wz2,
    const float* __restrict__ Wyu2, const float* __restrict__ byu2,
    const float* __restrict__ Wy2,
    const float* __restrict__ Wu2,  const float* __restrict__ b2)
{
    __shared__ float xs[DX_], u1s[DU_], u2s[DU_], red[256];
    const int n = blockIdx.x;
    const int k = threadIdx.x;

    if (k < DX_) xs[k] = X[n * DX_ + k];
    __syncthreads();

    float s = bt0[k];
    #pragma unroll 8
    for (int d = 0; d < DX_; d++) s = fmaf(xs[d], Wt0[k * DX_ + d], s);
    u1s[k] = fmaxf(s, 0.f);
    __syncthreads();

    s = bt1[k];
    #pragma unroll 8
    for (int z = 0; z < DU_; z++) s = fmaf(u1s[z], Wt1[k * DU_ + z], s);
    float u2v = fmaxf(s, 0.f);
    u2s[k] = u2v;

    if (k < DY_) {
        float t = byu0[k];
        #pragma unroll 8
        for (int d = 0; d < DX_; d++) t = fmaf(xs[d], Wyu0[k * DX_ + d], t);
        g_gy0[n * DY_ + k] = t;
        t = byu1[k];
        #pragma unroll 8
        for (int z = 0; z < DU_; z++) t = fmaf(u1s[z], Wyu1[k * DU_ + z], t);
        g_gy1[n * DY_ + k] = t;
    }
    s = b0[k];
    #pragma unroll 8
    for (int d = 0; d < DX_; d++) s = fmaf(xs[d], Wu0[k * DX_ + d], s);
    g_c0[n * DZ_ + k] = s;
    s = bzu1[k];
    #pragma unroll 8
    for (int z = 0; z < DU_; z++) s = fmaf(u1s[z], Wzu1[k * DU_ + z], s);
    g_gz1[n * DZ_ + k] = fmaxf(s, 0.f);
    s = b1[k];
    #pragma unroll 8
    for (int z = 0; z < DU_; z++) s = fmaf(u1s[z], Wu1[k * DU_ + z], s);
    g_c1[n * DZ_ + k] = s;
    __syncthreads();

    s = bzu2[k];
    #pragma unroll 8
    for (int z = 0; z < DU_; z++) s = fmaf(u2s[z], Wzu2[k * DU_ + z], s);
    g_gk2[n * DZ_ + k] = fmaxf(s, 0.f) * softplus_f(Wz2[k]);

    if (k < DY_) {
        float t = byu2[k];
        #pragma unroll 8
        for (int z = 0; z < DU_; z++) t = fmaf(u2s[z], Wyu2[k * DU_ + z], t);
        g_w2d[n * DY_ + k] = t * Wy2[k];
    }

    red[k] = u2v * Wu2[k];
    __syncthreads();
    for (int st = 128; st > 0; st >>= 1) {
        if (k < st) red[k] += red[k + st];
        __syncthreads();
    }
    if (k == 0) g_c2[n] = red[0] + b2[0];
}

// ---------------- kernel 2: fp16 HMMA GEMM + full phi + slack ----------------
// grid = (32, 128): x -> 64-row m-tile, y -> n.  CTA: 64m x 256k_out.
// 8 warps: wm = wid&1 (32 m rows), wq = wid>>1 (64 k cols).
// K loop: 8 chunks of 32 z + 1 pseudo chunk (rank-8 t1 term), double buffered.
// SMEM rows stride 80 B (40 halves) -> conflict-free frag loads.

#define SM_W     0          // 2 x 20480 (256 rows x 80B)
#define SM_A     40960      // 2 x 5120  (64 rows x 80B)
#define SM_WY0F  51200      // 256 x 12 floats = 12288
#define SM_C0    63488      // 256 floats
#define SM_GZ1   64512
#define SM_C1    65536
#define SM_GK2   66560
#define SM_GY1   67584      // 8 floats (pad 64)
#define SM_YW    67648      // 8 floats (pad 64)
#define SM_PHI   67712      // 256 floats
#define SMEM_BYTES 68736

extern __shared__ __align__(16) char smem[];

__device__ __forceinline__ void fill_A(char* Adst, int z0,
                                       const float* wy0f, const float* c0s,
                                       const float* gz1s, const float* ur,
                                       int mrow, int s)
{
    float o[8];
    #pragma unroll
    for (int jj = 0; jj < 8; ++jj) {
        const int rot = (jj + 2 * s) & 7;       // bank-rotation schedule
        const int z = z0 + s * 8 + rot;
        const float4 w0 = *(const float4*)(wy0f + z * 12);
        const float4 w1 = *(const float4*)(wy0f + z * 12 + 4);
        float v = c0s[z];
        v = fmaf(ur[0], w0.x, v); v = fmaf(ur[1], w0.y, v);
        v = fmaf(ur[2], w0.z, v); v = fmaf(ur[3], w0.w, v);
        v = fmaf(ur[4], w1.x, v); v = fmaf(ur[5], w1.y, v);
        v = fmaf(ur[6], w1.z, v); v = fmaf(ur[7], w1.w, v);
        o[rot] = fmaxf(v, 0.f) * gz1s[z];
    }
    uint4 pk;
    pk.x = pack_h2(o[0], o[1]);
    pk.y = pack_h2(o[2], o[3]);
    pk.z = pack_h2(o[4], o[5]);
    pk.w = pack_h2(o[6], o[7]);
    *(uint4*)(Adst + mrow * 80 + s * 16) = pk;
}

__global__ __launch_bounds__(256, 2) void main_mma_kernel(
    const float* __restrict__ U,
    const float* __restrict__ Y,
    const float* __restrict__ Wy0,
    const float* __restrict__ Wy1)
{
    const int tid  = threadIdx.x;
    const int lane = tid & 31;
    const int wid  = tid >> 5;
    const int g    = lane >> 2;     // groupID
    const int t4   = lane & 3;      // thread-in-group
    const int wm   = wid & 1;       // warp m-group (32 rows)
    const int wq   = wid >> 1;      // warp k-col group (64 cols)
    const int n    = blockIdx.y;
    const int m0   = blockIdx.x * 64;

    float* wy0f = (float*)(smem + SM_WY0F);
    float* c0s  = (float*)(smem + SM_C0);
    float* gz1s = (float*)(smem + SM_GZ1);
    float* c1s  = (float*)(smem + SM_C1);
    float* gk2s = (float*)(smem + SM_GK2);
    float* gy1s = (float*)(smem + SM_GY1);
    float* yws  = (float*)(smem + SM_YW);
    float* phiB = (float*)(smem + SM_PHI);
    const uint32_t sb = smem_u32(smem);

    // A-fill assignment: one m row (64 rows / 64 lane-groups), one z octet
    const int mrow = wid * 8 + (lane >> 2);  // 0..63
    const int s    = lane & 3;               // z sub-group 0..3

    // ---- kick off W chunk 0 cp.async ----
    {
        const uint32_t Wdst = sb + SM_W;     // buf 0
        #pragma unroll
        for (int it = 0; it < 4; ++it) {
            int idx = it * 256 + tid;
            int q = idx >> 2, seg = idx & 3;
            CP_ASYNC16(Wdst + (uint32_t)(q * 80 + seg * 16),
                       &g_sp1h[q * 256 + seg * 8]);
        }
        CP_COMMIT();
    }

    // ---- prologue: per-n consts ----
    c0s[tid]  = g_c0 [n * DZ_ + tid];
    gz1s[tid] = g_gz1[n * DZ_ + tid];
    c1s[tid]  = g_c1 [n * DZ_ + tid];
    gk2s[tid] = g_gk2[n * DZ_ + tid];
    if (tid < DY_) {
        gy1s[tid] = g_gy1[n * DY_ + tid];
        yws[tid]  = Y[n * DY_ + tid] - g_w2d[n * DY_ + tid];
    }
    {   // wy0f[z][d] = Wy0[z][d] * gy0[n][d], stride 12 floats
        const int z = tid;
        float4 wa = *(const float4*)&Wy0[z * 8];
        float4 wb = *(const float4*)&Wy0[z * 8 + 4];
        float4 ga = *(const float4*)&g_gy0[n * DY_];
        float4 gb = *(const float4*)&g_gy0[n * DY_ + 4];
        *(float4*)(wy0f + z * 12)     = make_float4(wa.x*ga.x, wa.y*ga.y, wa.z*ga.z, wa.w*ga.w);
        *(float4*)(wy0f + z * 12 + 4) = make_float4(wb.x*gb.x, wb.y*gb.y, wb.z*gb.z, wb.w*gb.w);
    }
    float ur[8];
    {
        float4 u0 = *(const float4*)&U[(m0 + mrow) * 8];
        float4 u1 = *(const float4*)&U[(m0 + mrow) * 8 + 4];
        ur[0]=u0.x; ur[1]=u0.y; ur[2]=u0.z; ur[3]=u0.w;
        ur[4]=u1.x; ur[5]=u1.y; ur[6]=u1.z; ur[7]=u1.w;
    }
    __syncthreads();

    // fill A chunk 0 (buf 0)
    fill_A(smem + SM_A, 0, wy0f, c0s, gz1s, ur, mrow, s);
    CP_WAIT0();
    __syncthreads();

    float acc[2][8][4];
    #pragma unroll
    for (int i = 0; i < 2; ++i)
        #pragma unroll
        for (int j = 0; j < 8; ++j)
            #pragma unroll
            for (int q = 0; q < 4; ++q) acc[i][j][q] = 0.f;

    // ---- main loop: 8 real chunks + 1 pseudo chunk ----
    for (int c = 0; c < 9; ++c) {
        const int buf = c & 1, nb = buf ^ 1;

        if (c < 8) {
            char* Adst = smem + SM_A + nb * 5120;
            if (c + 1 < 8) {
                const int z0n = (c + 1) * 32;
                const uint32_t Wdst = sb + SM_W + nb * 20480;
                #pragma unroll
                for (int it = 0; it < 4; ++it) {
                    int idx = it * 256 + tid;
                    int q = idx >> 2, seg = idx & 3;
                    CP_ASYNC16(Wdst + (uint32_t)(q * 80 + seg * 16),
                               &g_sp1h[q * 256 + z0n + seg * 8]);
                }
                CP_COMMIT();
                fill_A(Adst, z0n, wy0f, c0s, gz1s, ur, mrow, s);
            } else {
                // pseudo chunk: A[m][d<8]=fp16(U[m,d]); W[q][d<8]=fp16(Wy1[q,d]*gy1[d])
                const uint4 z4 = make_uint4(0, 0, 0, 0);
                uint4 av = z4;
                if (s == 0) {
                    av.x = pack_h2(ur[0], ur[1]);
                    av.y = pack_h2(ur[2], ur[3]);
                    av.z = pack_h2(ur[4], ur[5]);
                    av.w = pack_h2(ur[6], ur[7]);
                }
                *(uint4*)(Adst + mrow * 80 + s * 16) = av;

                char* Wdst = smem + SM_W + nb * 20480;
                const int q = tid;
                float4 w0 = *(const float4*)&Wy1[q * 8];
                float4 w1 = *(const float4*)&Wy1[q * 8 + 4];
                uint4 wv;
                wv.x = pack_h2(w0.x * gy1s[0], w0.y * gy1s[1]);
                wv.y = pack_h2(w0.z * gy1s[2], w0.w * gy1s[3]);
                wv.z = pack_h2(w1.x * gy1s[4], w1.y * gy1s[5]);
                wv.w = pack_h2(w1.z * gy1s[6], w1.w * gy1s[7]);
                *(uint4*)(Wdst + q * 80)      = wv;
                *(uint4*)(Wdst + q * 80 + 16) = z4;
                *(uint4*)(Wdst + q * 80 + 32) = z4;
                *(uint4*)(Wdst + q * 80 + 48) = z4;
                CP_COMMIT();   // empty group so CP_WAIT0 below is uniform
            }
        }

        // MMA on current buffer
        {
            const char* Ab = smem + SM_A + buf * 5120;
            const char* Wb = smem + SM_W + buf * 20480;
            #pragma unroll
            for (int ks = 0; ks < 2; ++ks) {
                uint32_t afr[2][4];
                #pragma unroll
                for (int i = 0; i < 2; ++i) {
                    const char* base = Ab + (wm * 32 + i * 16 + g) * 80 + t4 * 4 + ks * 32;
                    afr[i][0] = *(const uint32_t*)(base);
                    afr[i][1] = *(const uint32_t*)(base + 8 * 80);
                    afr[i][2] = *(const uint32_t*)(base + 16);
                    afr[i][3] = *(const uint32_t*)(base + 8 * 80 + 16);
                }
                #pragma unroll
                for (int j = 0; j < 8; ++j) {
                    const char* bb = Wb + (wq * 64 + j * 8 + g) * 80 + t4 * 4 + ks * 32;
                    uint32_t b0 = *(const uint32_t*)(bb);
                    uint32_t b1 = *(const uint32_t*)(bb + 16);
                    mma_f16(acc[0][j], afr[0], b0, b1);
                    mma_f16(acc[1][j], afr[1], b0, b1);
                }
            }
        }
        if (c < 8) CP_WAIT0();
        __syncthreads();
    }

    // ---- epilogue: phi over this CTA's full 256 k ----
    float p[4] = {0.f, 0.f, 0.f, 0.f};
    #pragma unroll
    for (int j = 0; j < 8; ++j) {
        const int q = wq * 64 + j * 8 + 2 * t4;
        const float ca = c1s[q],  cb = c1s[q + 1];
        const float ga = gk2s[q], gb = gk2s[q + 1];
        #pragma unroll
        for (int i = 0; i < 2; ++i) {
            p[i*2+0] = fmaf(fmaxf(acc[i][j][0] + ca, 0.f), ga, p[i*2+0]);
            p[i*2+0] = fmaf(fmaxf(acc[i][j][1] + cb, 0.f), gb, p[i*2+0]);
            p[i*2+1] = fmaf(fmaxf(acc[i][j][2] + ca, 0.f), ga, p[i*2+1]);
            p[i*2+1] = fmaf(fmaxf(acc[i][j][3] + cb, 0.f), gb, p[i*2+1]);
        }
    }
    #pragma unroll
    for (int idx = 0; idx < 4; ++idx) {
        float v = p[idx];
        v += __shfl_xor_sync(0xffffffffu, v, 1);
        v += __shfl_xor_sync(0xffffffffu, v, 2);
        if (t4 == 0) {
            const int i = idx >> 1, h = idx & 1;
            phiB[wq * 64 + wm * 32 + i * 16 + h * 8 + g] = v;
        }
    }
    __syncthreads();
    if (tid < 64) {
        float phi = phiB[tid] + phiB[64 + tid] + phiB[128 + tid] + phiB[192 + tid];
        float4 u0 = *(const float4*)&U[(m0 + tid) * 8];
        float4 u1 = *(const float4*)&U[(m0 + tid) * 8 + 4];
        float sl = -g_c2[n] - phi;
        sl = fmaf(u0.x, yws[0], sl); sl = fmaf(u0.y, yws[1], sl);
        sl = fmaf(u0.z, yws[2], sl); sl = fmaf(u0.w, yws[3], sl);
        sl = fmaf(u1.x, yws[4], sl); sl = fmaf(u1.y, yws[5], sl);
        sl = fmaf(u1.z, yws[6], sl); sl = fmaf(u1.w, yws[7], sl);
        g_slack[n * M_ + m0 + tid] = sl;
    }
}

// ---------------- kernel 3: row-wise stable logsumexp ----------------
__global__ void lse_kernel(float* __restrict__ out) {
    __shared__ float wred[8];
    __shared__ float bmax_s;
    const int n = blockIdx.x, tid = threadIdx.x;
    const int lane = tid & 31, warp = tid >> 5;

    float s[8];
    #pragma unroll
    for (int i = 0; i < 8; i++) s[i] = g_slack[n * M_ + tid + i * 256];

    float mx = s[0];
    #pragma unroll
    for (int i = 1; i < 8; i++) mx = fmaxf(mx, s[i]);
    #pragma unroll
    for (int off = 16; off; off >>= 1)
        mx = fmaxf(mx, __shfl_xor_sync(0xffffffffu, mx, off));
    if (lane == 0) wred[warp] = mx;
    __syncthreads();
    if (tid == 0) {
        float m2 = wred[0];
        #pragma unroll
        for (int w = 1; w < 8; w++) m2 = fmaxf(m2, wred[w]);
        bmax_s = m2;
    }
    __syncthreads();
    const float bmax = bmax_s;

    float sum = 0.f;
    #pragma unroll
    for (int i = 0; i < 8; i++) sum += expf((s[i] - bmax) * 100.f);
    #pragma unroll
    for (int off = 16; off; off >>= 1)
        sum += __shfl_xor_sync(0xffffffffu, sum, off);
    __syncthreads();
    if (lane == 0) wred[warp] = sum;
    __syncthreads();
    if (tid == 0) {
        float tot = 0.f;
        #pragma unroll
        for (int w = 0; w < 8; w++) tot += wred[w];
        out[n] = 0.01f * (logf(tot) - logf(2048.0f)) + bmax;
    }
}

// ---------------- launch ----------------
extern "C" void kernel_launch(void* const* d_in, const int* in_sizes, int n_in,
                              void* d_out, int out_size) {
    const float* X    = (const float*)d_in[0];
    const float* U    = (const float*)d_in[1];
    const float* Y    = (const float*)d_in[2];
    const float* Wt0  = (const float*)d_in[3];
    const float* bt0  = (const float*)d_in[4];
    const float* Wt1  = (const float*)d_in[5];
    const float* bt1  = (const float*)d_in[6];
    const float* Wyu0 = (const float*)d_in[7];
    const float* byu0 = (const float*)d_in[8];
    const float* Wy0  = (const float*)d_in[9];
    const float* Wu0  = (const float*)d_in[10];
    const float* b0   = (const float*)d_in[11];
    const float* Wzu1 = (const float*)d_in[12];
    const float* bzu1 = (const float*)d_in[13];
    const float* Wz1  = (const float*)d_in[14];
    const float* Wyu1 = (const float*)d_in[15];
    const float* byu1 = (const float*)d_in[16];
    const float* Wy1  = (const float*)d_in[17];
    const float* Wu1  = (const float*)d_in[18];
    const float* b1   = (const float*)d_in[19];
    const float* Wzu2 = (const float*)d_in[20];
    const float* bzu2 = (const float*)d_in[21];
    const float* Wz2  = (const float*)d_in[22];
    const float* Wyu2 = (const float*)d_in[23];
    const float* byu2 = (const float*)d_in[24];
    const float* Wy2  = (const float*)d_in[25];
    const float* Wu2  = (const float*)d_in[26];
    const float* b2   = (const float*)d_in[27];

    cudaFuncSetAttribute(main_mma_kernel,
                         cudaFuncAttributeMaxDynamicSharedMemorySize, SMEM_BYTES);

    sp1_kernel<<<256, 256>>>(Wz1);
    setup_kernel<<<128, 256>>>(X, Wt0, bt0, Wt1, bt1, Wyu0, byu0, Wu0, b0,
                               Wzu1, bzu1, Wyu1, byu1, Wu1, b1,
                               Wzu2, bzu2, Wz2, Wyu2, byu2, Wy2, Wu2, b2);
    dim3 grid(32, 128);
    main_mma_kernel<<<grid, 256, SMEM_BYTES>>>(U, Y, Wy0, Wy1);
    lse_kernel<<<128, 256>>>((float*)d_out);
}

// round 8
// speedup vs baseline: 2.9647x; 1.0351x over previous
#include <cuda_runtime.h>
#include <cuda_fp16.h>
#include <math.h>
#include <stdint.h>

// Problem dims
#define N_  128
#define M_  2048
#define DX_ 64
#define DY_ 8
#define DU_ 256
#define DZ_ 256

// ---------------- device scratch (static, no allocations) ----------------
__device__ __align__(16) __half g_sp1h[DZ_ * DZ_];  // fp16(softplus(Wz1)) [k][z]
__device__ __align__(16) float g_gy0[N_ * DY_];
__device__ __align__(16) float g_c0 [N_ * DZ_];
__device__ __align__(16) float g_gz1[N_ * DZ_];
__device__ __align__(16) float g_gy1[N_ * DY_];
__device__ __align__(16) float g_c1 [N_ * DZ_];
__device__ __align__(16) float g_gk2[N_ * DZ_];     // gz2 * softplus(Wz2)
__device__ __align__(16) float g_w2d[N_ * DY_];     // gy2 * Wy2
__device__ __align__(16) float g_c2 [N_];
__device__ __align__(16) float g_slack[N_ * M_];

__device__ __forceinline__ float softplus_f(float x) {
    return fmaxf(x, 0.f) + log1pf(expf(-fabsf(x)));
}

#define CP_ASYNC16(dst, src) \
    asm volatile("cp.async.cg.shared.global [%0], [%1], 16;" \
        :: "r"((uint32_t)(dst)), "l"(src) : "memory")
#define CP_COMMIT() asm volatile("cp.async.commit_group;" ::: "memory")
#define CP_WAIT0()  asm volatile("cp.async.wait_group 0;" ::: "memory")

__device__ __forceinline__ uint32_t smem_u32(const void* p) {
    uint32_t a;
    asm("{ .reg .u64 t; cvta.to.shared.u64 t, %1; cvt.u32.u64 %0, t; }"
        : "=r"(a) : "l"(p));
    return a;
}

// m16n8k16 fp16 MMA, fp32 accumulate
__device__ __forceinline__ void mma_f16(float* c, const uint32_t* a,
                                        uint32_t b0, uint32_t b1) {
    asm volatile(
        "mma.sync.aligned.m16n8k16.row.col.f32.f16.f16.f32 "
        "{%0,%1,%2,%3}, {%4,%5,%6,%7}, {%8,%9}, {%0,%1,%2,%3};"
        : "+f"(c[0]), "+f"(c[1]), "+f"(c[2]), "+f"(c[3])
        : "r"(a[0]), "r"(a[1]), "r"(a[2]), "r"(a[3]), "r"(b0), "r"(b1));
}

#define LDSM_X4(r0, r1, r2, r3, addr) \
    asm volatile("ldmatrix.sync.aligned.m8n8.x4.shared.b16 {%0,%1,%2,%3}, [%4];" \
        : "=r"(r0), "=r"(r1), "=r"(r2), "=r"(r3) : "r"(addr))

__device__ __forceinline__ uint32_t pack_h2(float lo, float hi) {
    __half2 h = __floats2half2_rn(lo, hi);
    return *(uint32_t*)&h;
}

// ---------------- kernel 0: fp16(softplus(Wz1)) ----------------
__global__ void sp1_kernel(const float* __restrict__ Wz1) {
    int i = blockIdx.x * 256 + threadIdx.x;
    g_sp1h[i] = __float2half_rn(softplus_f(Wz1[i]));
}

// ---------------- kernel 1: per-n setup ----------------
__global__ void setup_kernel(
    const float* __restrict__ X,
    const float* __restrict__ Wt0,  const float* __restrict__ bt0,
    const float* __restrict__ Wt1,  const float* __restrict__ bt1,
    const float* __restrict__ Wyu0, const float* __restrict__ byu0,
    const float* __restrict__ Wu0,  const float* __restrict__ b0,
    const float* __restrict__ Wzu1, const float* __restrict__ bzu1,
    const float* __restrict__ Wyu1, const float* __restrict__ byu1,
    const float* __restrict__ Wu1,  const float* __restrict__ b1,
    const float* __restrict__ Wzu2, const float* __restrict__ bzu2,
    const float* __restrict__ Wz2,
    const float* __restrict__ Wyu2, const float* __restrict__ byu2,
    const float* __restrict__ Wy2,
    const float* __restrict__ Wu2,  const float* __restrict__ b2)
{
    __shared__ float xs[DX_], u1s[DU_], u2s[DU_], red[256];
    const int n = blockIdx.x;
    const int k = threadIdx.x;

    if (k < DX_) xs[k] = X[n * DX_ + k];
    __syncthreads();

    float s = bt0[k];
    #pragma unroll 8
    for (int d = 0; d < DX_; d++) s = fmaf(xs[d], Wt0[k * DX_ + d], s);
    u1s[k] = fmaxf(s, 0.f);
    __syncthreads();

    s = bt1[k];
    #pragma unroll 8
    for (int z = 0; z < DU_; z++) s = fmaf(u1s[z], Wt1[k * DU_ + z], s);
    float u2v = fmaxf(s, 0.f);
    u2s[k] = u2v;

    if (k < DY_) {
        float t = byu0[k];
        #pragma unroll 8
        for (int d = 0; d < DX_; d++) t = fmaf(xs[d], Wyu0[k * DX_ + d], t);
        g_gy0[n * DY_ + k] = t;
        t = byu1[k];
        #pragma unroll 8
        for (int z = 0; z < DU_; z++) t = fmaf(u1s[z], Wyu1[k * DU_ + z], t);
        g_gy1[n * DY_ + k] = t;
    }
    s = b0[k];
    #pragma unroll 8
    for (int d = 0; d < DX_; d++) s = fmaf(xs[d], Wu0[k * DX_ + d], s);
    g_c0[n * DZ_ + k] = s;
    s = bzu1[k];
    #pragma unroll 8
    for (int z = 0; z < DU_; z++) s = fmaf(u1s[z], Wzu1[k * DU_ + z], s);
    g_gz1[n * DZ_ + k] = fmaxf(s, 0.f);
    s = b1[k];
    #pragma unroll 8
    for (int z = 0; z < DU_; z++) s = fmaf(u1s[z], Wu1[k * DU_ + z], s);
    g_c1[n * DZ_ + k] = s;
    __syncthreads();

    s = bzu2[k];
    #pragma unroll 8
    for (int z = 0; z < DU_; z++) s = fmaf(u2s[z], Wzu2[k * DU_ + z], s);
    g_gk2[n * DZ_ + k] = fmaxf(s, 0.f) * softplus_f(Wz2[k]);

    if (k < DY_) {
        float t = byu2[k];
        #pragma unroll 8
        for (int z = 0; z < DU_; z++) t = fmaf(u2s[z], Wyu2[k * DU_ + z], t);
        g_w2d[n * DY_ + k] = t * Wy2[k];
    }

    red[k] = u2v * Wu2[k];
    __syncthreads();
    for (int st = 128; st > 0; st >>= 1) {
        if (k < st) red[k] += red[k + st];
        __syncthreads();
    }
    if (k == 0) g_c2[n] = red[0] + b2[0];
}

// ---------------- kernel 2: fp16 HMMA GEMM + full phi + slack ----------------
// grid = (32, 128): x -> 64-row m-tile, y -> n.  CTA: 64m x 256k_out.
// 8 warps: wm = wid&1 (32 m rows), wq = wid>>1 (64 k cols).
// K loop: 4 chunks of 64 z + 1 k16 pseudo chunk; double buffered, ldmatrix frags.
// Row stride 144 B (9 x 16B) -> conflict-free ldmatrix.

#define RS    144                   // row stride bytes
#define SM_W     0                  // 2 x 256*144 = 73728
#define SM_A     73728              // 2 x 64*144  = 18432
#define SM_WY0F  92160              // 256 x 12 floats = 12288
#define SM_C0    104448             // 256 floats
#define SM_GZ1   105472
#define SM_C1    106496
#define SM_GK2   107520
#define SM_GY1   108544             // 8 floats (pad 64B)
#define SM_YW    108608
#define SM_PHI   108672             // 256 floats
#define SMEM_BYTES 109696
#define WBUF  36864                 // 256*144
#define ABUF  9216                  // 64*144

extern __shared__ __align__(16) char smem[];

// fill one 64-z A chunk: thread owns row mrow, z quarter s (16 z)
__device__ __forceinline__ void fill_A64(char* Adst, int z0,
                                         const float* wy0f, const float* c0s,
                                         const float* gz1s, const float* ur,
                                         int mrow, int s)
{
    float o[16];
    #pragma unroll
    for (int jj = 0; jj < 16; ++jj) {
        const int j = (jj + s) & 15;           // bank-rotation schedule
        const int z = z0 + s * 16 + j;
        const float4 w0 = *(const float4*)(wy0f + z * 12);
        const float4 w1 = *(const float4*)(wy0f + z * 12 + 4);
        float v = c0s[z];
        v = fmaf(ur[0], w0.x, v); v = fmaf(ur[1], w0.y, v);
        v = fmaf(ur[2], w0.z, v); v = fmaf(ur[3], w0.w, v);
        v = fmaf(ur[4], w1.x, v); v = fmaf(ur[5], w1.y, v);
        v = fmaf(ur[6], w1.z, v); v = fmaf(ur[7], w1.w, v);
        o[j] = fmaxf(v, 0.f) * gz1s[z];
    }
    uint4 p0, p1;
    p0.x = pack_h2(o[0],  o[1]);  p0.y = pack_h2(o[2],  o[3]);
    p0.z = pack_h2(o[4],  o[5]);  p0.w = pack_h2(o[6],  o[7]);
    p1.x = pack_h2(o[8],  o[9]);  p1.y = pack_h2(o[10], o[11]);
    p1.z = pack_h2(o[12], o[13]); p1.w = pack_h2(o[14], o[15]);
    char* dst = Adst + mrow * RS + s * 32;
    *(uint4*)(dst)      = p0;
    *(uint4*)(dst + 16) = p1;
}

__global__ __launch_bounds__(256, 2) void main_mma_kernel(
    const float* __restrict__ U,
    const float* __restrict__ Y,
    const float* __restrict__ Wy0,
    const float* __restrict__ Wy1)
{
    const int tid  = threadIdx.x;
    const int lane = tid & 31;
    const int wid  = tid >> 5;
    const int g    = lane >> 2;     // groupID
    const int t4   = lane & 3;      // thread-in-group
    const int wm   = wid & 1;       // warp m-group (32 rows)
    const int wq   = wid >> 1;      // warp k-col group (64 cols)
    const int n    = blockIdx.y;
    const int m0   = blockIdx.x * 64;

    float* wy0f = (float*)(smem + SM_WY0F);
    float* c0s  = (float*)(smem + SM_C0);
    float* gz1s = (float*)(smem + SM_GZ1);
    float* c1s  = (float*)(smem + SM_C1);
    float* gk2s = (float*)(smem + SM_GK2);
    float* gy1s = (float*)(smem + SM_GY1);
    float* yws  = (float*)(smem + SM_YW);
    float* phiB = (float*)(smem + SM_PHI);
    const uint32_t sb = smem_u32(smem);

    // A-fill assignment
    const int mrow = tid >> 2;      // 0..63
    const int s    = tid & 3;       // z quarter

    // ldmatrix per-lane base addresses (buf 0; add buf offset + ks*32 at use)
    const int mi = lane >> 3, r = lane & 7;
    uint32_t a_base[2], b_base[4];
    #pragma unroll
    for (int i = 0; i < 2; ++i)
        a_base[i] = sb + SM_A + (uint32_t)((wm * 32 + i * 16 + (mi & 1) * 8 + r) * RS
                                           + (mi >> 1) * 16);
    #pragma unroll
    for (int jp = 0; jp < 4; ++jp)
        b_base[jp] = sb + SM_W + (uint32_t)((wq * 64 + jp * 16 + (mi >> 1) * 8 + r) * RS
                                            + (mi & 1) * 16);

    // ---- kick off W chunk 0 cp.async ----
    {
        const uint32_t Wdst = sb + SM_W;
        #pragma unroll
        for (int it = 0; it < 8; ++it) {
            int idx = it * 256 + tid;
            int q = idx >> 3, seg = idx & 7;
            CP_ASYNC16(Wdst + (uint32_t)(q * RS + seg * 16),
                       &g_sp1h[q * 256 + seg * 8]);
        }
        CP_COMMIT();
    }

    // ---- prologue: per-n consts ----
    c0s[tid]  = g_c0 [n * DZ_ + tid];
    gz1s[tid] = g_gz1[n * DZ_ + tid];
    c1s[tid]  = g_c1 [n * DZ_ + tid];
    gk2s[tid] = g_gk2[n * DZ_ + tid];
    if (tid < DY_) {
        gy1s[tid] = g_gy1[n * DY_ + tid];
        yws[tid]  = Y[n * DY_ + tid] - g_w2d[n * DY_ + tid];
    }
    {   // wy0f[z][d] = Wy0[z][d] * gy0[n][d], stride 12 floats
        const int z = tid;
        float4 wa = *(const float4*)&Wy0[z * 8];
        float4 wb = *(const float4*)&Wy0[z * 8 + 4];
        float4 ga = *(const float4*)&g_gy0[n * DY_];
        float4 gb = *(const float4*)&g_gy0[n * DY_ + 4];
        *(float4*)(wy0f + z * 12)     = make_float4(wa.x*ga.x, wa.y*ga.y, wa.z*ga.z, wa.w*ga.w);
        *(float4*)(wy0f + z * 12 + 4) = make_float4(wb.x*gb.x, wb.y*gb.y, wb.z*gb.z, wb.w*gb.w);
    }
    float ur[8];
    {
        float4 u0 = *(const float4*)&U[(m0 + mrow) * 8];
        float4 u1 = *(const float4*)&U[(m0 + mrow) * 8 + 4];
        ur[0]=u0.x; ur[1]=u0.y; ur[2]=u0.z; ur[3]=u0.w;
        ur[4]=u1.x; ur[5]=u1.y; ur[6]=u1.z; ur[7]=u1.w;
    }
    __syncthreads();

    fill_A64(smem + SM_A, 0, wy0f, c0s, gz1s, ur, mrow, s);
    CP_WAIT0();
    __syncthreads();

    float acc[2][8][4];
    #pragma unroll
    for (int i = 0; i < 2; ++i)
        #pragma unroll
        for (int j = 0; j < 8; ++j)
            #pragma unroll
            for (int q = 0; q < 4; ++q) acc[i][j][q] = 0.f;

    // ---- main loop: 4 real 64-z chunks + 1 pseudo k16 chunk ----
    #pragma unroll
    for (int c = 0; c < 5; ++c) {
        const int buf = c & 1, nb = buf ^ 1;

        if (c < 4) {
            if (c + 1 < 4) {
                const int z0n = (c + 1) * 64;
                const uint32_t Wdst = sb + SM_W + nb * WBUF;
                #pragma unroll
                for (int it = 0; it < 8; ++it) {
                    int idx = it * 256 + tid;
                    int q = idx >> 3, seg = idx & 7;
                    CP_ASYNC16(Wdst + (uint32_t)(q * RS + seg * 16),
                               &g_sp1h[q * 256 + z0n + seg * 8]);
                }
                CP_COMMIT();
                fill_A64(smem + SM_A + nb * ABUF, z0n, wy0f, c0s, gz1s, ur, mrow, s);
            } else {
                // pseudo chunk (k16): A[m][0..7]=U, 8..15=0; W[q][0..7]=Wy1*gy1
                char* Adst = smem + SM_A + nb * ABUF;
                if (s == 0) {
                    uint4 av, zv;
                    av.x = pack_h2(ur[0], ur[1]); av.y = pack_h2(ur[2], ur[3]);
                    av.z = pack_h2(ur[4], ur[5]); av.w = pack_h2(ur[6], ur[7]);
                    zv = make_uint4(0, 0, 0, 0);
                    *(uint4*)(Adst + mrow * RS)      = av;
                    *(uint4*)(Adst + mrow * RS + 16) = zv;
                }
                char* Wdst = smem + SM_W + nb * WBUF;
                const int q = tid;
                float4 w0 = *(const float4*)&Wy1[q * 8];
                float4 w1 = *(const float4*)&Wy1[q * 8 + 4];
                uint4 wv;
                wv.x = pack_h2(w0.x * gy1s[0], w0.y * gy1s[1]);
                wv.y = pack_h2(w0.z * gy1s[2], w0.w * gy1s[3]);
                wv.z = pack_h2(w1.x * gy1s[4], w1.y * gy1s[5]);
                wv.w = pack_h2(w1.z * gy1s[6], w1.w * gy1s[7]);
                *(uint4*)(Wdst + q * RS)      = wv;
                *(uint4*)(Wdst + q * RS + 16) = make_uint4(0, 0, 0, 0);
            }
        }

        // MMA on current buffer
        {
            const uint32_t aoff = buf * ABUF;
            const uint32_t woff = buf * WBUF;
            const int nks = (c == 4) ? 1 : 4;
            #pragma unroll
            for (int ks = 0; ks < 4; ++ks) {
                if (ks >= nks) break;
                const uint32_t kb = ks * 32;
                uint32_t a0[4], a1[4];
                LDSM_X4(a0[0], a0[1], a0[2], a0[3], a_base[0] + aoff + kb);
                LDSM_X4(a1[0], a1[1], a1[2], a1[3], a_base[1] + aoff + kb);
                #pragma unroll
                for (int jp = 0; jp < 4; ++jp) {
                    uint32_t b[4];
                    LDSM_X4(b[0], b[1], b[2], b[3], b_base[jp] + woff + kb);
                    mma_f16(acc[0][jp * 2],     a0, b[0], b[1]);
                    mma_f16(acc[1][jp * 2],     a1, b[0], b[1]);
                    mma_f16(acc[0][jp * 2 + 1], a0, b[2], b[3]);
                    mma_f16(acc[1][jp * 2 + 1], a1, b[2], b[3]);
                }
            }
        }
        if (c < 3) CP_WAIT0();
        __syncthreads();
    }

    // ---- epilogue: phi over this CTA's full 256 k ----
    float p[4] = {0.f, 0.f, 0.f, 0.f};
    #pragma unroll
    for (int j = 0; j < 8; ++j) {
        const int q = wq * 64 + j * 8 + 2 * t4;
        const float ca = c1s[q],  cb = c1s[q + 1];
        const float ga = gk2s[q], gb = gk2s[q + 1];
        #pragma unroll
        for (int i = 0; i < 2; ++i) {
            p[i*2+0] = fmaf(fmaxf(acc[i][j][0] + ca, 0.f), ga, p[i*2+0]);
            p[i*2+0] = fmaf(fmaxf(acc[i][j][1] + cb, 0.f), gb, p[i*2+0]);
            p[i*2+1] = fmaf(fmaxf(acc[i][j][2] + ca, 0.f), ga, p[i*2+1]);
            p[i*2+1] = fmaf(fmaxf(acc[i][j][3] + cb, 0.f), gb, p[i*2+1]);
        }
    }
    #pragma unroll
    for (int idx = 0; idx < 4; ++idx) {
        float v = p[idx];
        v += __shfl_xor_sync(0xffffffffu, v, 1);
        v += __shfl_xor_sync(0xffffffffu, v, 2);
        if (t4 == 0) {
            const int i = idx >> 1, h = idx & 1;
            phiB[wq * 64 + wm * 32 + i * 16 + h * 8 + g] = v;
        }
    }
    __syncthreads();
    if (tid < 64) {
        float phi = phiB[tid] + phiB[64 + tid] + phiB[128 + tid] + phiB[192 + tid];
        float4 u0 = *(const float4*)&U[(m0 + tid) * 8];
        float4 u1 = *(const float4*)&U[(m0 + tid) * 8 + 4];
        float sl = -g_c2[n] - phi;
        sl = fmaf(u0.x, yws[0], sl); sl = fmaf(u0.y, yws[1], sl);
        sl = fmaf(u0.z, yws[2], sl); sl = fmaf(u0.w, yws[3], sl);
        sl = fmaf(u1.x, yws[4], sl); sl = fmaf(u1.y, yws[5], sl);
        sl = fmaf(u1.z, yws[6], sl); sl = fmaf(u1.w, yws[7], sl);
        g_slack[n * M_ + m0 + tid] = sl;
    }
}

// ---------------- kernel 3: row-wise stable logsumexp ----------------
__global__ void lse_kernel(float* __restrict__ out) {
    __shared__ float wred[8];
    __shared__ float bmax_s;
    const int n = blockIdx.x, tid = threadIdx.x;
    const int lane = tid & 31, warp = tid >> 5;

    float s[8];
    #pragma unroll
    for (int i = 0; i < 8; i++) s[i] = g_slack[n * M_ + tid + i * 256];

    float mx = s[0];
    #pragma unroll
    for (int i = 1; i < 8; i++) mx = fmaxf(mx, s[i]);
    #pragma unroll
    for (int off = 16; off; off >>= 1)
        mx = fmaxf(mx, __shfl_xor_sync(0xffffffffu, mx, off));
    if (lane == 0) wred[warp] = mx;
    __syncthreads();
    if (tid == 0) {
        float m2 = wred[0];
        #pragma unroll
        for (int w = 1; w < 8; w++) m2 = fmaxf(m2, wred[w]);
        bmax_s = m2;
    }
    __syncthreads();
    const float bmax = bmax_s;

    float sum = 0.f;
    #pragma unroll
    for (int i = 0; i < 8; i++) sum += expf((s[i] - bmax) * 100.f);
    #pragma unroll
    for (int off = 16; off; off >>= 1)
        sum += __shfl_xor_sync(0xffffffffu, sum, off);
    __syncthreads();
    if (lane == 0) wred[warp] = sum;
    __syncthreads();
    if (tid == 0) {
        float tot = 0.f;
        #pragma unroll
        for (int w = 0; w < 8; w++) tot += wred[w];
        out[n] = 0.01f * (logf(tot) - logf(2048.0f)) + bmax;
    }
}

// ---------------- launch ----------------
extern "C" void kernel_launch(void* const* d_in, const int* in_sizes, int n_in,
                              void* d_out, int out_size) {
    const float* X    = (const float*)d_in[0];
    const float* U    = (const float*)d_in[1];
    const float* Y    = (const float*)d_in[2];
    const float* Wt0  = (const float*)d_in[3];
    const float* bt0  = (const float*)d_in[4];
    const float* Wt1  = (const float*)d_in[5];
    const float* bt1  = (const float*)d_in[6];
    const float* Wyu0 = (const float*)d_in[7];
    const float* byu0 = (const float*)d_in[8];
    const float* Wy0  = (const float*)d_in[9];
    const float* Wu0  = (const float*)d_in[10];
    const float* b0   = (const float*)d_in[11];
    const float* Wzu1 = (const float*)d_in[12];
    const float* bzu1 = (const float*)d_in[13];
    const float* Wz1  = (const float*)d_in[14];
    const float* Wyu1 = (const float*)d_in[15];
    const float* byu1 = (const float*)d_in[16];
    const float* Wy1  = (const float*)d_in[17];
    const float* Wu1  = (const float*)d_in[18];
    const float* b1   = (const float*)d_in[19];
    const float* Wzu2 = (const float*)d_in[20];
    const float* bzu2 = (const float*)d_in[21];
    const float* Wz2  = (const float*)d_in[22];
    const float* Wyu2 = (const float*)d_in[23];
    const float* byu2 = (const float*)d_in[24];
    const float* Wy2  = (const float*)d_in[25];
    const float* Wu2  = (const float*)d_in[26];
    const float* b2   = (const float*)d_in[27];

    cudaFuncSetAttribute(main_mma_kernel,
                         cudaFuncAttributeMaxDynamicSharedMemorySize, SMEM_BYTES);

    sp1_kernel<<<256, 256>>>(Wz1);
    setup_kernel<<<128, 256>>>(X, Wt0, bt0, Wt1, bt1, Wyu0, byu0, Wu0, b0,
                               Wzu1, bzu1, Wyu1, byu1, Wu1, b1,
                               Wzu2, bzu2, Wz2, Wyu2, byu2, Wy2, Wu2, b2);
    dim3 grid(32, 128);
    main_mma_kernel<<<grid, 256, SMEM_BYTES>>>(U, Y, Wy0, Wy1);
    lse_kernel<<<128, 256>>>((float*)d_out);
}